// round 1
// baseline (speedup 1.0000x reference)
#include <cuda_runtime.h>

// PrimitiveGate: apply 4x4 gate matrix to qubit axes (5,13) of a
// (2,)*24 + (4,) float32 state tensor.
//
// Layout: state is row-major over (q0..q23, batch). Float index of
// (bits, batch) = config*4 + batch, so with float4 pointers each config
// is one element. Qubit q -> bit (23-q) of config: q5 -> bit 18, q13 -> bit 10.
//
// Each thread handles one base config (bits 10 and 18 clear), reads the
// 4 amplitudes at {base, base+2^10, base+2^18, base+2^10+2^18}, applies
// the matrix per batch lane, writes 4 outputs. 512 MB total traffic.

#define S1 (1u << 10)   // qubit 13 stride (float4 units)
#define S0 (1u << 18)   // qubit 5  stride (float4 units)

__global__ __launch_bounds__(256)
void gate_kernel(const float4* __restrict__ state,
                 const float* __restrict__ M,
                 float4* __restrict__ out) {
    unsigned t = blockIdx.x * blockDim.x + threadIdx.x;  // [0, 2^22)

    // deposit zeros at bits 10 and 18
    unsigned i0 = t & 0x3FFu;            // bits 0..9
    unsigned i1 = (t >> 10) & 0x7Fu;     // -> bits 11..17
    unsigned i2 = t >> 17;               // -> bits 19..23
    unsigned base = i0 | (i1 << 11) | (i2 << 19);

    // gate matrix: row = a0*2+a1 (a0 = q5 out-bit, a1 = q13 out-bit),
    //              col = s0*2+s1 (s0 = q5 in-bit,  s1 = q13 in-bit)
    float m[16];
#pragma unroll
    for (int i = 0; i < 16; i++) m[i] = __ldg(M + i);

    float4 x00 = state[base];            // s0=0,s1=0 -> col 0
    float4 x01 = state[base + S1];       // s0=0,s1=1 -> col 1
    float4 x10 = state[base + S0];       // s0=1,s1=0 -> col 2
    float4 x11 = state[base + S0 + S1];  // s0=1,s1=1 -> col 3

#define APPLY(row)                                                        \
    make_float4(                                                          \
        fmaf(m[4*(row)+0], x00.x, fmaf(m[4*(row)+1], x01.x,               \
          fmaf(m[4*(row)+2], x10.x, m[4*(row)+3] * x11.x))),              \
        fmaf(m[4*(row)+0], x00.y, fmaf(m[4*(row)+1], x01.y,               \
          fmaf(m[4*(row)+2], x10.y, m[4*(row)+3] * x11.y))),              \
        fmaf(m[4*(row)+0], x00.z, fmaf(m[4*(row)+1], x01.z,               \
          fmaf(m[4*(row)+2], x10.z, m[4*(row)+3] * x11.z))),              \
        fmaf(m[4*(row)+0], x00.w, fmaf(m[4*(row)+1], x01.w,               \
          fmaf(m[4*(row)+2], x10.w, m[4*(row)+3] * x11.w))))

    out[base]           = APPLY(0);  // a0=0,a1=0
    out[base + S1]      = APPLY(1);  // a0=0,a1=1
    out[base + S0]      = APPLY(2);  // a0=1,a1=0
    out[base + S0 + S1] = APPLY(3);  // a0=1,a1=1
#undef APPLY
}

extern "C" void kernel_launch(void* const* d_in, const int* in_sizes, int n_in,
                              void* d_out, int out_size) {
    const float4* state = (const float4*)d_in[0];
    const float*  M     = (const float*)d_in[1];
    float4*       out   = (float4*)d_out;

    const unsigned n_threads = 1u << 22;      // 2^24 configs / 4 per thread
    const unsigned block = 256;
    gate_kernel<<<n_threads / block, block>>>(state, M, out);
}

// round 2
// speedup vs baseline: 1.0004x; 1.0004x over previous
#include <cuda_runtime.h>

// PrimitiveGate: 4x4 gate on qubit axes (5,13) of a (2,)^24 + (4,) fp32 state.
// q5 -> bit 18, q13 -> bit 10 of the float4-config index.
// HBM-bound: 512 MB mandatory traffic. This version doubles per-thread MLP
// (2 configs = 8 outstanding LDG.128) and uses streaming cache hints.

#define S1 (1u << 10)   // qubit 13 stride (float4 units)
#define S0 (1u << 18)   // qubit 5  stride (float4 units)

__device__ __forceinline__ float4 ldcs4(const float4* p) {
    return __ldcs(p);
}

__device__ __forceinline__ unsigned deposit(unsigned c) {
    // insert zero bits at positions 10 and 18 of a 22-bit index
    return (c & 0x3FFu) | (((c >> 10) & 0x7Fu) << 11) | ((c >> 17) << 19);
}

__global__ __launch_bounds__(256)
void gate_kernel(const float4* __restrict__ state,
                 const float* __restrict__ M,
                 float4* __restrict__ out) {
    unsigned t = blockIdx.x * blockDim.x + threadIdx.x;  // [0, 2^21)

    unsigned baseA = deposit(t);
    unsigned baseB = deposit(t + (1u << 21));

    float m[16];
#pragma unroll
    for (int i = 0; i < 16; i++) m[i] = __ldg(M + i);

    // issue all 8 loads up front (MLP=8)
    float4 a00 = ldcs4(state + baseA);
    float4 a01 = ldcs4(state + baseA + S1);
    float4 a10 = ldcs4(state + baseA + S0);
    float4 a11 = ldcs4(state + baseA + S0 + S1);
    float4 b00 = ldcs4(state + baseB);
    float4 b01 = ldcs4(state + baseB + S1);
    float4 b10 = ldcs4(state + baseB + S0);
    float4 b11 = ldcs4(state + baseB + S0 + S1);

#define APPLY(row, x00, x01, x10, x11)                                    \
    make_float4(                                                          \
        fmaf(m[4*(row)+0], x00.x, fmaf(m[4*(row)+1], x01.x,               \
          fmaf(m[4*(row)+2], x10.x, m[4*(row)+3] * x11.x))),              \
        fmaf(m[4*(row)+0], x00.y, fmaf(m[4*(row)+1], x01.y,               \
          fmaf(m[4*(row)+2], x10.y, m[4*(row)+3] * x11.y))),              \
        fmaf(m[4*(row)+0], x00.z, fmaf(m[4*(row)+1], x01.z,               \
          fmaf(m[4*(row)+2], x10.z, m[4*(row)+3] * x11.z))),              \
        fmaf(m[4*(row)+0], x00.w, fmaf(m[4*(row)+1], x01.w,               \
          fmaf(m[4*(row)+2], x10.w, m[4*(row)+3] * x11.w))))

    float4 r;
    r = APPLY(0, a00, a01, a10, a11); __stcs(out + baseA,           r);
    r = APPLY(1, a00, a01, a10, a11); __stcs(out + baseA + S1,      r);
    r = APPLY(2, a00, a01, a10, a11); __stcs(out + baseA + S0,      r);
    r = APPLY(3, a00, a01, a10, a11); __stcs(out + baseA + S0 + S1, r);

    r = APPLY(0, b00, b01, b10, b11); __stcs(out + baseB,           r);
    r = APPLY(1, b00, b01, b10, b11); __stcs(out + baseB + S1,      r);
    r = APPLY(2, b00, b01, b10, b11); __stcs(out + baseB + S0,      r);
    r = APPLY(3, b00, b01, b10, b11); __stcs(out + baseB + S0 + S1, r);
#undef APPLY
}

extern "C" void kernel_launch(void* const* d_in, const int* in_sizes, int n_in,
                              void* d_out, int out_size) {
    const float4* state = (const float4*)d_in[0];
    const float*  M     = (const float*)d_in[1];
    float4*       out   = (float4*)d_out;

    const unsigned n_threads = 1u << 21;   // 2 configs per thread
    const unsigned block = 256;
    gate_kernel<<<n_threads / block, block>>>(state, M, out);
}